// round 1
// baseline (speedup 1.0000x reference)
#include <cuda_runtime.h>

#define N_SAMP 384
#define M 12
#define NP 6
#define UCOLS (M * NP)   // 72 complex entries per sample

// Scratch: feature-unitary slices. g_u1[i][k][b] = U1_i[k][b];
// g_u2[j][k][a] = conj(U2_j[k][a]).  (k = mode row 0..11, a/b = photon col 0..5)
__device__ float2 g_u1[N_SAMP * UCOLS];
__device__ float2 g_u2[N_SAMP * UCOLS];

__device__ __forceinline__ float2 cmul(float2 a, float2 b) {
    return make_float2(a.x * b.x - a.y * b.y, a.x * b.y + a.y * b.x);
}

// ---------------------------------------------------------------------------
// Stage 1: U(x) = A @ diag(exp(i x)) @ B, keep first NP columns.
// One block per sample, 160 threads (144 used for loads, 72 for compute).
// ---------------------------------------------------------------------------
__global__ void build_u_kernel(const float* __restrict__ x,
                               const float* __restrict__ A_re,
                               const float* __restrict__ A_im,
                               const float* __restrict__ B_re,
                               const float* __restrict__ B_im,
                               int conj_flag)
{
    __shared__ float2 ph[M];
    __shared__ float2 sA[M * M];
    __shared__ float2 sB[M][NP];

    const int s   = blockIdx.x;
    const int tid = threadIdx.x;

    if (tid < M * M) sA[tid] = make_float2(A_re[tid], A_im[tid]);
    if (tid < M * NP) {
        int b = tid / NP, c = tid - b * NP;
        sB[b][c] = make_float2(B_re[b * M + c], B_im[b * M + c]);
    }
    if (tid < M) {
        float sn, cs;
        sincosf(x[s * M + tid], &sn, &cs);
        ph[tid] = make_float2(cs, sn);
    }
    __syncthreads();

    if (tid < M * NP) {
        const int a = tid / NP;
        const int c = tid - a * NP;
        float2 acc = make_float2(0.f, 0.f);
#pragma unroll
        for (int b = 0; b < M; ++b) {
            float2 t  = cmul(ph[b], sB[b][c]);   // ph_b * B[b][c]
            float2 Av = sA[a * M + b];
            acc.x += Av.x * t.x - Av.y * t.y;
            acc.y += Av.x * t.y + Av.y * t.x;
        }
        if (conj_flag) {
            acc.y = -acc.y;
            g_u2[s * UCOLS + tid] = acc;
        } else {
            g_u1[s * UCOLS + tid] = acc;
        }
    }
}

// ---------------------------------------------------------------------------
// Stage 2: per pair (i,j): W[a][b] = sum_k conjU2[j][k][a] * U1[i][k][b],
// then Glynn permanent with Gray-code rowsum updates, K = |perm|^2.
// Block = 256 threads = 16(i) x 16(j) pair tile.
// ---------------------------------------------------------------------------
#define SPITCH 73   // per-sample smem pitch (float2) — odd-ish to avoid bank conflicts

__global__ __launch_bounds__(256) void pair_kernel(float* __restrict__ out)
{
    __shared__ float2 s1[16 * SPITCH];
    __shared__ float2 s2[16 * SPITCH];

    const int i0  = blockIdx.y * 16;
    const int j0  = blockIdx.x * 16;
    const int tid = threadIdx.x;

    // Cooperative load of 16 U1 rows and 16 U2 rows (72 float2 each).
    for (int e = tid; e < 16 * UCOLS; e += 256) {
        int li = e / UCOLS;
        int r  = e - li * UCOLS;
        s1[li * SPITCH + r] = g_u1[(i0 + li) * UCOLS + r];
        s2[li * SPITCH + r] = g_u2[(j0 + li) * UCOLS + r];
    }
    __syncthreads();

    const int lj = tid & 15;        // j varies fastest -> coalesced output
    const int li = tid >> 4;
    const float2* __restrict__ p1 = &s1[li * SPITCH];
    const float2* __restrict__ p2 = &s2[lj * SPITCH];

    float2 W[NP][NP];
#pragma unroll
    for (int a = 0; a < NP; ++a)
#pragma unroll
        for (int b = 0; b < NP; ++b)
            W[a][b] = make_float2(0.f, 0.f);

#pragma unroll
    for (int k = 0; k < M; ++k) {
        float2 a6[NP], b6[NP];
#pragma unroll
        for (int a = 0; a < NP; ++a) a6[a] = p2[k * NP + a];
#pragma unroll
        for (int b = 0; b < NP; ++b) b6[b] = p1[k * NP + b];
#pragma unroll
        for (int a = 0; a < NP; ++a)
#pragma unroll
            for (int b = 0; b < NP; ++b) {
                W[a][b].x += a6[a].x * b6[b].x - a6[a].y * b6[b].y;
                W[a][b].y += a6[a].x * b6[b].y + a6[a].y * b6[b].x;
            }
    }

    // Glynn permanent (n=6, 32 sign vectors), Gray-code order.
    float2 r[NP];
#pragma unroll
    for (int j = 0; j < NP; ++j) {
        r[j] = W[0][j];
#pragma unroll
        for (int a = 1; a < NP; ++a) {
            r[j].x += W[a][j].x;
            r[j].y += W[a][j].y;
        }
    }

    // balanced-tree complex product of 6 rowsums
    float2 acc;
    {
        float2 p01 = cmul(r[0], r[1]);
        float2 p23 = cmul(r[2], r[3]);
        float2 p45 = cmul(r[4], r[5]);
        acc = cmul(cmul(p01, p23), p45);
    }

#pragma unroll
    for (int t = 1; t < 32; ++t) {
        // compile-time: which gray bit flips, and its new sign
        const int bit = (t & 1) ? 0 : ((t & 2) ? 1 : ((t & 4) ? 2 : ((t & 8) ? 3 : 4)));
        const int a   = bit + 1;                       // row whose sign flips (rows 1..5)
        const float s2v = (((t ^ (t >> 1)) >> bit) & 1) ? -2.f : 2.f;
        const float sg  = (t & 1) ? -1.f : 1.f;        // parity = (-1)^t

#pragma unroll
        for (int j = 0; j < NP; ++j) {
            r[j].x += s2v * W[a][j].x;
            r[j].y += s2v * W[a][j].y;
        }
        float2 p01 = cmul(r[0], r[1]);
        float2 p23 = cmul(r[2], r[3]);
        float2 p45 = cmul(r[4], r[5]);
        float2 p   = cmul(cmul(p01, p23), p45);
        acc.x += sg * p.x;
        acc.y += sg * p.y;
    }

    // perm = acc / 32 ; K = |perm|^2 = |acc|^2 / 1024
    const float K = (acc.x * acc.x + acc.y * acc.y) * (1.0f / 1024.0f);
    out[(i0 + li) * N_SAMP + (j0 + lj)] = K;
}

// ---------------------------------------------------------------------------
extern "C" void kernel_launch(void* const* d_in, const int* in_sizes, int n_in,
                              void* d_out, int out_size)
{
    const float* x1   = (const float*)d_in[0];
    const float* x2   = (const float*)d_in[1];
    const float* A_re = (const float*)d_in[2];
    const float* A_im = (const float*)d_in[3];
    const float* B_re = (const float*)d_in[4];
    const float* B_im = (const float*)d_in[5];

    build_u_kernel<<<N_SAMP, 160>>>(x1, A_re, A_im, B_re, B_im, 0);
    build_u_kernel<<<N_SAMP, 160>>>(x2, A_re, A_im, B_re, B_im, 1);

    dim3 grid(N_SAMP / 16, N_SAMP / 16);   // 24 x 24
    pair_kernel<<<grid, 256>>>((float*)d_out);
}

// round 3
// speedup vs baseline: 1.1659x; 1.1659x over previous
#include <cuda_runtime.h>

#define N_SAMP 384
#define M 12
#define NP 6
#define UC (M * NP)      // 72 complex entries per sample

typedef unsigned long long u64;

// g_u1[i][k][b] = U1_i[k][b] (plain float2)
// g_u2d: duplicated-format conj(U2): per entry two packed f32x2 vectors
//   v0 = (re, re), v1 = (-im, im)   where (re,im) = conj(U2)[j][k][a]
__device__ float2 g_u1[N_SAMP * UC];
__device__ float2 g_u2d[N_SAMP * UC * 2];

__device__ __forceinline__ float2 cmul(float2 a, float2 b) {
    return make_float2(a.x * b.x - a.y * b.y, a.x * b.y + a.y * b.x);
}

// ---- packed f32x2 helpers (Blackwell FFMA2 path, u64 carrier) ----
__device__ __forceinline__ u64 pk2(float lo, float hi) {
    u64 d; asm("mov.b64 %0, {%1,%2};" : "=l"(d) : "f"(lo), "f"(hi)); return d;
}
__device__ __forceinline__ float2 upk(u64 d) {
    float2 r; asm("mov.b64 {%0,%1}, %2;" : "=f"(r.x), "=f"(r.y) : "l"(d)); return r;
}
__device__ __forceinline__ u64 ffma2(u64 a, u64 b, u64 c) {
    u64 d; asm("fma.rn.f32x2 %0, %1, %2, %3;" : "=l"(d) : "l"(a), "l"(b), "l"(c)); return d;
}
__device__ __forceinline__ u64 fadd2(u64 a, u64 b) {
    u64 d; asm("add.rn.f32x2 %0, %1, %2;" : "=l"(d) : "l"(a), "l"(b)); return d;
}

// ---------------------------------------------------------------------------
// Stage 1 (single launch, grid=768): U(x) = A @ diag(exp(ix)) @ B, first NP cols.
// Blocks [0,384) -> x1 -> g_u1 plain; blocks [384,768) -> x2 -> conj + duplicate.
// ---------------------------------------------------------------------------
__global__ void build_u_kernel(const float* __restrict__ x1,
                               const float* __restrict__ x2,
                               const float* __restrict__ A_re,
                               const float* __restrict__ A_im,
                               const float* __restrict__ B_re,
                               const float* __restrict__ B_im)
{
    __shared__ float2 ph[M];
    __shared__ float2 sA[M * M];
    __shared__ float2 sB[M][NP];

    const int s      = blockIdx.x;
    const int tid    = threadIdx.x;
    const int second = (s >= N_SAMP);
    const int ss     = second ? s - N_SAMP : s;
    const float* x   = second ? x2 : x1;

    if (tid < M * M) sA[tid] = make_float2(A_re[tid], A_im[tid]);
    if (tid < M * NP) {
        int b = tid / NP, c = tid - b * NP;
        sB[b][c] = make_float2(B_re[b * M + c], B_im[b * M + c]);
    }
    if (tid < M) {
        float sn, cs;
        sincosf(x[ss * M + tid], &sn, &cs);
        ph[tid] = make_float2(cs, sn);
    }
    __syncthreads();

    if (tid < M * NP) {
        const int a = tid / NP;
        const int c = tid - a * NP;
        float2 acc = make_float2(0.f, 0.f);
#pragma unroll
        for (int b = 0; b < M; ++b) {
            float2 t  = cmul(ph[b], sB[b][c]);
            float2 Av = sA[a * M + b];
            acc.x += Av.x * t.x - Av.y * t.y;
            acc.y += Av.x * t.y + Av.y * t.x;
        }
        if (second) {
            // c = conj(acc) = (acc.x, -acc.y); v0=(c.x,c.x), v1=(-c.y,c.y)
            g_u2d[(ss * UC + tid) * 2 + 0] = make_float2(acc.x, acc.x);
            g_u2d[(ss * UC + tid) * 2 + 1] = make_float2(acc.y, -acc.y);
        } else {
            g_u1[ss * UC + tid] = acc;
        }
    }
}

// ---------------------------------------------------------------------------
// Stage 2: per pair (i,j): W[a][b] = sum_k conjU2[j][k][a] * U1[i][k][b]  (FFMA2)
// then Glynn permanent (Gray-code), K = |perm|^2. 16x16 pair tile per block.
// ---------------------------------------------------------------------------
#define P1 73    // s1 pitch in float2
#define P2 145   // s2 pitch in u64

__device__ __forceinline__ float2 prod6(const u64* r) {
    float2 a0 = upk(r[0]), a1 = upk(r[1]), a2 = upk(r[2]);
    float2 a3 = upk(r[3]), a4 = upk(r[4]), a5 = upk(r[5]);
    float2 p01 = cmul(a0, a1);
    float2 p23 = cmul(a2, a3);
    float2 p45 = cmul(a4, a5);
    return cmul(cmul(p01, p23), p45);
}

__global__ __launch_bounds__(256, 1) void pair_kernel(float* __restrict__ out)
{
    __shared__ float2 s1[16 * P1];
    __shared__ u64 s2[16 * P2];

    const int i0  = blockIdx.y * 16;
    const int j0  = blockIdx.x * 16;
    const int tid = threadIdx.x;

    const u64* __restrict__ gu2 = (const u64*)g_u2d;
    for (int e = tid; e < 16 * (UC * 2); e += 256) {
        int lj = e / (UC * 2);
        int r  = e - lj * (UC * 2);
        s2[lj * P2 + r] = gu2[(j0 + lj) * (UC * 2) + r];
    }
    for (int e = tid; e < 16 * UC; e += 256) {
        int li = e / UC;
        int r  = e - li * UC;
        s1[li * P1 + r] = g_u1[(i0 + li) * UC + r];
    }
    __syncthreads();

    const int lj = tid & 15;          // j fastest -> coalesced output
    const int li = tid >> 4;
    const float2* __restrict__ p1 = &s1[li * P1];
    const u64* __restrict__ p2 = &s2[lj * P2];

    u64 W[NP][NP];
#pragma unroll
    for (int a = 0; a < NP; ++a)
#pragma unroll
        for (int b = 0; b < NP; ++b)
            W[a][b] = 0ull;   // bit pattern = two fp32 zeros

#pragma unroll
    for (int k = 0; k < M; ++k) {
        u64 va0[NP], va1[NP], bp[NP], bs[NP];
#pragma unroll
        for (int a = 0; a < NP; ++a) {
            va0[a] = p2[(k * NP + a) * 2 + 0];
            va1[a] = p2[(k * NP + a) * 2 + 1];
        }
#pragma unroll
        for (int b = 0; b < NP; ++b) {
            float2 b2 = p1[k * NP + b];
            bp[b] = pk2(b2.x, b2.y);
            bs[b] = pk2(b2.y, b2.x);
        }
#pragma unroll
        for (int a = 0; a < NP; ++a)
#pragma unroll
            for (int b = 0; b < NP; ++b) {
                W[a][b] = ffma2(va0[a], bp[b], W[a][b]);
                W[a][b] = ffma2(va1[a], bs[b], W[a][b]);
            }
    }

    // Glynn permanent (n=6, 32 sign vectors), Gray-code updates, packed r.
    const u64 PL2 = pk2(2.f, 2.f);
    const u64 MI2 = pk2(-2.f, -2.f);

    u64 r[NP];
#pragma unroll
    for (int j = 0; j < NP; ++j) {
        u64 t = fadd2(W[0][j], W[1][j]);
        t = fadd2(t, W[2][j]);
        t = fadd2(t, W[3][j]);
        t = fadd2(t, W[4][j]);
        r[j] = fadd2(t, W[5][j]);
    }

    float2 acc = prod6(r);

#pragma unroll
    for (int t = 1; t < 32; ++t) {
        const int bit = (t & 1) ? 0 : ((t & 2) ? 1 : ((t & 4) ? 2 : ((t & 8) ? 3 : 4)));
        const int a   = bit + 1;                               // flipped row (1..5)
        const bool neg = (((t ^ (t >> 1)) >> bit) & 1) != 0;   // new delta = -1 ?
        const u64 c2 = neg ? MI2 : PL2;
        const float sg  = (t & 1) ? -1.f : 1.f;                // parity (-1)^t

#pragma unroll
        for (int j = 0; j < NP; ++j)
            r[j] = ffma2(c2, W[a][j], r[j]);

        float2 p = prod6(r);
        acc.x += sg * p.x;
        acc.y += sg * p.y;
    }

    const float K = (acc.x * acc.x + acc.y * acc.y) * (1.0f / 1024.0f);
    out[(i0 + li) * N_SAMP + (j0 + lj)] = K;
}

// ---------------------------------------------------------------------------
extern "C" void kernel_launch(void* const* d_in, const int* in_sizes, int n_in,
                              void* d_out, int out_size)
{
    const float* x1   = (const float*)d_in[0];
    const float* x2   = (const float*)d_in[1];
    const float* A_re = (const float*)d_in[2];
    const float* A_im = (const float*)d_in[3];
    const float* B_re = (const float*)d_in[4];
    const float* B_im = (const float*)d_in[5];

    build_u_kernel<<<2 * N_SAMP, 160>>>(x1, x2, A_re, A_im, B_re, B_im);

    dim3 grid(N_SAMP / 16, N_SAMP / 16);   // 24 x 24
    pair_kernel<<<grid, 256>>>((float*)d_out);
}